// round 1
// baseline (speedup 1.0000x reference)
#include <cuda_runtime.h>
#include <math.h>

// ---------------- problem constants ----------------
constexpr int NB     = 32;
constexpr int NC     = 128;
constexpr int NH     = 64;
constexpr int NWp    = 64;          // image width
constexpr int WSZ    = 8;
constexpr int SHIFT  = 4;
constexpr int NHEADS = 4;
constexpr int DH     = 32;
constexpr int TOK    = 64;          // tokens per window
constexpr int NWIN   = 64;          // windows per image
constexpr int NPIX   = NH * NWp;    // 4096
constexpr int NTOK   = NB * NPIX;   // 131072
constexpr int HID    = 512;
constexpr int MH     = 256;

// ---------------- device scratch (no allocations allowed) ----------------
__device__ float g_xt  [NTOK * NC];        // x transposed to token-major  [B*HW, C]
__device__ float g_qkv [NTOK * 3 * NC];    // window-order rows            [B*NW*TOK, 384]
__device__ float g_att [NTOK * NC];        // attention out (window order) [.,128]
__device__ float g_skip[NTOK * NC];        // post-LN1 residual (image order)
__device__ float g_ffn1[NTOK * HID];
__device__ float g_y   [NTOK * NC];        // final token-major result
__device__ float g_bias[NHEADS * TOK * TOK];

// ---------------- K0: [B,C,HW] -> [B,HW,C] ----------------
__global__ void k_transpose_in(const float* __restrict__ x) {
    __shared__ float tile[32][33];
    int b  = blockIdx.z;
    int p0 = blockIdx.x * 32;
    int c0 = blockIdx.y * 32;
    int tx = threadIdx.x, ty = threadIdx.y;   // 32 x 8
#pragma unroll
    for (int i = 0; i < 32; i += 8)
        tile[ty + i][tx] = x[(b * NC + c0 + ty + i) * NPIX + p0 + tx];
    __syncthreads();
#pragma unroll
    for (int i = 0; i < 32; i += 8)
        g_xt[(b * NPIX + p0 + ty + i) * NC + c0 + tx] = tile[tx][ty + i];
}

// ---------------- K7: [B,HW,C] -> [B,C,HW] ----------------
__global__ void k_transpose_out(float* __restrict__ out) {
    __shared__ float tile[32][33];
    int b  = blockIdx.z;
    int p0 = blockIdx.x * 32;
    int c0 = blockIdx.y * 32;
    int tx = threadIdx.x, ty = threadIdx.y;
#pragma unroll
    for (int i = 0; i < 32; i += 8)
        tile[ty + i][tx] = g_y[(b * NPIX + p0 + ty + i) * NC + c0 + tx];
    __syncthreads();
#pragma unroll
    for (int i = 0; i < 32; i += 8)
        out[(b * NC + c0 + ty + i) * NPIX + p0 + tx] = tile[tx][ty + i];
}

// ---------------- K1: meta-network relative-position bias ----------------
__global__ void k_meta_bias(const float* __restrict__ w1, const float* __restrict__ b1,
                            const float* __restrict__ w2, const float* __restrict__ b2) {
    int p = blockIdx.x * 256 + threadIdx.x;          // 0..4095 -> (qi, kj)
    if (p >= TOK * TOK) return;
    int qi = p >> 6, kj = p & 63;
    float d0 = (float)((qi >> 3) - (kj >> 3));
    float d1 = (float)((qi & 7) - (kj & 7));
    float r0 = (d0 > 0.f) ? log1pf(d0) : (d0 < 0.f ? -log1pf(-d0) : 0.f);
    float r1 = (d1 > 0.f) ? log1pf(d1) : (d1 < 0.f ? -log1pf(-d1) : 0.f);
    float acc0 = 0.f, acc1 = 0.f, acc2 = 0.f, acc3 = 0.f;
    for (int j = 0; j < MH; j++) {
        float h = fmaf(r0, w1[j], fmaf(r1, w1[MH + j], b1[j]));
        h = fmaxf(h, 0.f);
        acc0 = fmaf(h, w2[j * 4 + 0], acc0);
        acc1 = fmaf(h, w2[j * 4 + 1], acc1);
        acc2 = fmaf(h, w2[j * 4 + 2], acc2);
        acc3 = fmaf(h, w2[j * 4 + 3], acc3);
    }
    g_bias[0 * 4096 + p] = acc0 + b2[0];
    g_bias[1 * 4096 + p] = acc1 + b2[1];
    g_bias[2 * 4096 + p] = acc2 + b2[2];
    g_bias[3 * 4096 + p] = acc3 + b2[3];
}

// ---------------- K3: windowed cosine attention ----------------
__global__ void __launch_bounds__(256) k_attn(const float* __restrict__ tau) {
    __shared__ float sq[TOK][DH + 1];
    __shared__ float sk[TOK][DH + 1];
    __shared__ float sv[TOK][DH + 1];
    __shared__ float ss[TOK][TOK + 1];
    __shared__ float sqn[TOK], skn[TOK];
    __shared__ int   sreg[TOK];

    int gw   = blockIdx.x;          // global window id, 0..2047
    int head = blockIdx.y;          // 0..3
    int tid  = threadIdx.x;
    int win  = gw & 63;
    int wh   = win >> 3, ww = win & 7;
    int rowbase = gw * TOK;
    int qoff = head * DH;

    // load q, k, v tiles (float4, coalesced)
    for (int idx = tid; idx < TOK * (DH / 4); idx += 256) {
        int t  = idx >> 3;
        int d4 = (idx & 7) * 4;
        const float* rp = g_qkv + (size_t)(rowbase + t) * (3 * NC);
        float4 q4 = *(const float4*)(rp + qoff + d4);
        float4 k4 = *(const float4*)(rp + NC + qoff + d4);
        float4 v4 = *(const float4*)(rp + 2 * NC + qoff + d4);
        sq[t][d4 + 0] = q4.x; sq[t][d4 + 1] = q4.y; sq[t][d4 + 2] = q4.z; sq[t][d4 + 3] = q4.w;
        sk[t][d4 + 0] = k4.x; sk[t][d4 + 1] = k4.y; sk[t][d4 + 2] = k4.z; sk[t][d4 + 3] = k4.w;
        sv[t][d4 + 0] = v4.x; sv[t][d4 + 1] = v4.y; sv[t][d4 + 2] = v4.z; sv[t][d4 + 3] = v4.w;
    }
    if (tid < TOK) {
        int th = tid >> 3, tw = tid & 7;
        int hs = wh * WSZ + th, wsc = ww * WSZ + tw;
        int rh = (hs  >= NH  - SHIFT) ? 2 : ((hs  >= NH  - WSZ) ? 1 : 0);
        int rw = (wsc >= NWp - SHIFT) ? 2 : ((wsc >= NWp - WSZ) ? 1 : 0);
        sreg[tid] = rh * 3 + rw;
    }
    __syncthreads();

    if (tid < TOK) {
        float s = 0.f;
#pragma unroll
        for (int d = 0; d < DH; d++) s = fmaf(sq[tid][d], sq[tid][d], s);
        sqn[tid] = sqrtf(s);
    } else if (tid < 2 * TOK) {
        int t = tid - TOK;
        float s = 0.f;
#pragma unroll
        for (int d = 0; d < DH; d++) s = fmaf(sk[t][d], sk[t][d], s);
        skn[t] = sqrtf(s);
    }
    __syncthreads();

    float tinv = 1.0f / fmaxf(tau[head], 0.01f);
    const float* bptr = g_bias + head * TOK * TOK;
    for (int e = tid; e < TOK * TOK; e += 256) {
        int i = e >> 6, j = e & 63;
        float dot = 0.f;
#pragma unroll
        for (int d = 0; d < DH; d++) dot = fmaf(sq[i][d], sk[j][d], dot);
        float denom = fmaxf(sqn[i] * skn[j], 1e-6f);
        float s = dot / denom * tinv + bptr[e];
        if (sreg[i] != sreg[j]) s -= 100.0f;
        ss[i][j] = s;
    }
    __syncthreads();

    if (tid < TOK) {
        float mx = -1e30f;
#pragma unroll
        for (int j = 0; j < TOK; j++) mx = fmaxf(mx, ss[tid][j]);
        float sum = 0.f;
#pragma unroll
        for (int j = 0; j < TOK; j++) {
            float ex = expf(ss[tid][j] - mx);
            ss[tid][j] = ex;
            sum += ex;
        }
        float inv = 1.0f / sum;
#pragma unroll
        for (int j = 0; j < TOK; j++) ss[tid][j] *= inv;
    }
    __syncthreads();

    for (int e = tid; e < TOK * DH; e += 256) {
        int t = e >> 5, d = e & 31;
        float acc = 0.f;
#pragma unroll
        for (int j = 0; j < TOK; j++) acc = fmaf(ss[t][j], sv[j][d], acc);
        g_att[(size_t)(rowbase + t) * NC + qoff + d] = acc;
    }
}

// ---------------- fused SGEMM: 128x128 tile, BK=16, 8x8 microtile ----------------
// OP 0: QKV  (A = xt gathered via roll+window, N=384, K=128, +bias)
// OP 1: PROJ (A = att gathered via fold+unroll, N=128, K=128, +bias, LN1, +xt residual -> skip)
// OP 2: FFN1 (A = skip, N=512, K=128, +bias, exact GELU -> ffn1)
// OP 3: FFN2 (A = ffn1, N=128, K=512, +bias, LN2, +skip residual -> y)
template <int OP>
__global__ void __launch_bounds__(256, 2) k_gemm(const float* __restrict__ Wm,
                                                 const float* __restrict__ bias,
                                                 const float* __restrict__ lng,
                                                 const float* __restrict__ lnb) {
    constexpr int K = (OP == 3) ? 512 : 128;
    constexpr int N = (OP == 0) ? 384 : ((OP == 2) ? 512 : 128);

    __shared__ float As[16][128];
    __shared__ float Bs[16][128];
    __shared__ int   srow[128];

    const float* Aptr = (OP == 0) ? g_xt : (OP == 1) ? g_att : (OP == 2) ? g_skip : g_ffn1;
    float*       Cptr = (OP == 0) ? g_qkv : (OP == 1) ? g_skip : (OP == 2) ? g_ffn1 : g_y;
    const float* Rptr = (OP == 1) ? g_xt : g_skip;

    int tid = threadIdx.x;
    int m0  = blockIdx.x * 128;
    int n0  = blockIdx.y * 128;

    if (tid < 128) {
        int r = m0 + tid;
        int s;
        if (OP == 0) {
            // window-order row -> rolled source pixel in xt
            int b = r >> 12, win = (r >> 6) & 63, t = r & 63;
            int hs = ((win >> 3) << 3) + (t >> 3);
            int ws = ((win & 7) << 3) + (t & 7);
            int hsrc = (hs + SHIFT) & 63, wsrc = (ws + SHIFT) & 63;
            s = (b << 12) + (hsrc << 6) + wsrc;
        } else if (OP == 1) {
            // image-order row -> window-order row in att (fold + reverse roll)
            int b = r >> 12, h = (r >> 6) & 63, w = r & 63;
            int hs = (h - SHIFT) & 63, ws = (w - SHIFT) & 63;
            int win = ((hs >> 3) << 3) + (ws >> 3);
            int t   = ((hs & 7) << 3) + (ws & 7);
            s = (b << 12) + (win << 6) + t;
        } else {
            s = r;
        }
        srow[tid] = s;
    }

    int tx = tid & 15, ty = tid >> 4;
    float acc[8][8];
#pragma unroll
    for (int i = 0; i < 8; i++)
#pragma unroll
        for (int j = 0; j < 8; j++) acc[i][j] = 0.f;

    for (int k0 = 0; k0 < K; k0 += 16) {
        __syncthreads();
#pragma unroll
        for (int i = 0; i < 2; i++) {
            int gid = tid + i * 256;                   // 512 float4 of A
            int m  = gid >> 2;
            int kq = (gid & 3) << 2;
            float4 a = *(const float4*)(Aptr + (size_t)srow[m] * K + k0 + kq);
            As[kq + 0][m] = a.x; As[kq + 1][m] = a.y;
            As[kq + 2][m] = a.z; As[kq + 3][m] = a.w;
        }
#pragma unroll
        for (int i = 0; i < 2; i++) {
            int gid = tid + i * 256;                   // 512 float4 of B
            int kk = gid >> 5;
            int nq = (gid & 31) << 2;
            *(float4*)&Bs[kk][nq] = *(const float4*)(Wm + (size_t)(k0 + kk) * N + n0 + nq);
        }
        __syncthreads();
#pragma unroll
        for (int kk = 0; kk < 16; kk++) {
            float4 a0 = *(const float4*)&As[kk][ty * 4];
            float4 a1 = *(const float4*)&As[kk][64 + ty * 4];
            float4 b0 = *(const float4*)&Bs[kk][tx * 4];
            float4 b1 = *(const float4*)&Bs[kk][64 + tx * 4];
            float av[8] = {a0.x, a0.y, a0.z, a0.w, a1.x, a1.y, a1.z, a1.w};
            float bv[8] = {b0.x, b0.y, b0.z, b0.w, b1.x, b1.y, b1.z, b1.w};
#pragma unroll
            for (int i = 0; i < 8; i++)
#pragma unroll
                for (int j = 0; j < 8; j++) acc[i][j] = fmaf(av[i], bv[j], acc[i][j]);
        }
    }

    // ---- epilogue ----
    int nlo = n0 + tx * 4;           // columns j=0..3
    int nhi = n0 + 64 + tx * 4;      // columns j=4..7
    float4 blo = *(const float4*)(bias + nlo);
    float4 bhi = *(const float4*)(bias + nhi);
    float bv8[8] = {blo.x, blo.y, blo.z, blo.w, bhi.x, bhi.y, bhi.z, bhi.w};

#pragma unroll
    for (int i = 0; i < 8; i++) {
        int m = m0 + ((i < 4) ? (ty * 4 + i) : (64 + ty * 4 + i - 4));
#pragma unroll
        for (int j = 0; j < 8; j++) acc[i][j] += bv8[j];

        if constexpr (OP == 0 || OP == 2) {
            if constexpr (OP == 2) {
#pragma unroll
                for (int j = 0; j < 8; j++) {
                    float v = acc[i][j];
                    acc[i][j] = 0.5f * v * (1.0f + erff(v * 0.70710678118654752f));
                }
            }
            float4 lo = make_float4(acc[i][0], acc[i][1], acc[i][2], acc[i][3]);
            float4 hi = make_float4(acc[i][4], acc[i][5], acc[i][6], acc[i][7]);
            *(float4*)(Cptr + (size_t)m * N + nlo) = lo;
            *(float4*)(Cptr + (size_t)m * N + nhi) = hi;
        } else {
            // LayerNorm over the 128 outputs of row m (held by one half-warp)
            float s = 0.f;
#pragma unroll
            for (int j = 0; j < 8; j++) s += acc[i][j];
            s += __shfl_xor_sync(0xffffffffu, s, 1);
            s += __shfl_xor_sync(0xffffffffu, s, 2);
            s += __shfl_xor_sync(0xffffffffu, s, 4);
            s += __shfl_xor_sync(0xffffffffu, s, 8);
            float mean = s * (1.0f / 128.0f);
            float vs = 0.f;
#pragma unroll
            for (int j = 0; j < 8; j++) {
                float d = acc[i][j] - mean;
                vs = fmaf(d, d, vs);
            }
            vs += __shfl_xor_sync(0xffffffffu, vs, 1);
            vs += __shfl_xor_sync(0xffffffffu, vs, 2);
            vs += __shfl_xor_sync(0xffffffffu, vs, 4);
            vs += __shfl_xor_sync(0xffffffffu, vs, 8);
            float rstd = rsqrtf(vs * (1.0f / 128.0f) + 1e-5f);

            float4 glo = *(const float4*)(lng + nlo);
            float4 ghi = *(const float4*)(lng + nhi);
            float4 bl2 = *(const float4*)(lnb + nlo);
            float4 bh2 = *(const float4*)(lnb + nhi);
            float4 rlo = *(const float4*)(Rptr + (size_t)m * 128 + nlo);
            float4 rhi = *(const float4*)(Rptr + (size_t)m * 128 + nhi);
            float gg[8] = {glo.x, glo.y, glo.z, glo.w, ghi.x, ghi.y, ghi.z, ghi.w};
            float bb[8] = {bl2.x, bl2.y, bl2.z, bl2.w, bh2.x, bh2.y, bh2.z, bh2.w};
            float rr[8] = {rlo.x, rlo.y, rlo.z, rlo.w, rhi.x, rhi.y, rhi.z, rhi.w};
            float o[8];
#pragma unroll
            for (int j = 0; j < 8; j++)
                o[j] = (acc[i][j] - mean) * rstd * gg[j] + bb[j] + rr[j];
            float4 lo = make_float4(o[0], o[1], o[2], o[3]);
            float4 hi = make_float4(o[4], o[5], o[6], o[7]);
            *(float4*)(Cptr + (size_t)m * 128 + nlo) = lo;
            *(float4*)(Cptr + (size_t)m * 128 + nhi) = hi;
        }
    }
}

// ---------------- launch ----------------
extern "C" void kernel_launch(void* const* d_in, const int* in_sizes, int n_in,
                              void* d_out, int out_size) {
    const float* x      = (const float*)d_in[0];
    const float* qkv_w  = (const float*)d_in[1];
    const float* qkv_b  = (const float*)d_in[2];
    const float* proj_w = (const float*)d_in[3];
    const float* proj_b = (const float*)d_in[4];
    const float* mw1    = (const float*)d_in[5];
    const float* mb1    = (const float*)d_in[6];
    const float* mw2    = (const float*)d_in[7];
    const float* mb2    = (const float*)d_in[8];
    const float* tau    = (const float*)d_in[9];
    const float* ln1g   = (const float*)d_in[10];
    const float* ln1b   = (const float*)d_in[11];
    const float* ln2g   = (const float*)d_in[12];
    const float* ln2b   = (const float*)d_in[13];
    const float* fw1    = (const float*)d_in[14];
    const float* fb1    = (const float*)d_in[15];
    const float* fw2    = (const float*)d_in[16];
    const float* fb2    = (const float*)d_in[17];
    float* out = (float*)d_out;

    dim3 tb(32, 8);
    k_transpose_in<<<dim3(NPIX / 32, NC / 32, NB), tb>>>(x);
    k_meta_bias<<<16, 256>>>(mw1, mb1, mw2, mb2);
    k_gemm<0><<<dim3(NTOK / 128, 3), 256>>>(qkv_w, qkv_b, nullptr, nullptr);
    k_attn<<<dim3(NB * NWIN, NHEADS), 256>>>(tau);
    k_gemm<1><<<dim3(NTOK / 128, 1), 256>>>(proj_w, proj_b, ln1g, ln1b);
    k_gemm<2><<<dim3(NTOK / 128, 4), 256>>>(fw1, fb1, nullptr, nullptr);
    k_gemm<3><<<dim3(NTOK / 128, 1), 256>>>(fw2, fb2, ln2g, ln2b);
    k_transpose_out<<<dim3(NPIX / 32, NC / 32, NB), tb>>>(out);
}

// round 4
// speedup vs baseline: 1.1575x; 1.1575x over previous
#include <cuda_runtime.h>
#include <cuda_bf16.h>
#include <math.h>
#include <stdint.h>

// ---------------- problem constants ----------------
constexpr int NB     = 32;
constexpr int NC     = 128;
constexpr int NH     = 64;
constexpr int NWp    = 64;
constexpr int WSZ    = 8;
constexpr int SHIFT  = 4;
constexpr int NHEADS = 4;
constexpr int DH     = 32;
constexpr int TOK    = 64;
constexpr int NWIN   = 64;          // windows per image
constexpr int NPIX   = NH * NWp;    // 4096
constexpr int NTOK   = NB * NPIX;   // 131072
constexpr int HID    = 512;
constexpr int MH     = 256;

// ---------------- device scratch ----------------
__device__ float g_xt  [NTOK * NC];
__device__ float g_qkv [NTOK * 3 * NC];
__device__ float g_skip[NTOK * NC];
__device__ float g_y   [NTOK * NC];
__device__ float g_bias[NHEADS * TOK * TOK];

__device__ __nv_bfloat16 g_xth [NTOK * NC];
__device__ __nv_bfloat16 g_xtl [NTOK * NC];
__device__ __nv_bfloat16 g_atth[NTOK * NC];
__device__ __nv_bfloat16 g_attl[NTOK * NC];
__device__ __nv_bfloat16 g_skph[NTOK * NC];
__device__ __nv_bfloat16 g_skpl[NTOK * NC];
__device__ __nv_bfloat16 g_f1h [NTOK * HID];
__device__ __nv_bfloat16 g_f1l [NTOK * HID];

__device__ __nv_bfloat16 g_wqkvh[384 * 128], g_wqkvl[384 * 128];
__device__ __nv_bfloat16 g_wprjh[128 * 128], g_wprjl[128 * 128];
__device__ __nv_bfloat16 g_wf1h [512 * 128], g_wf1l [512 * 128];
__device__ __nv_bfloat16 g_wf2h [128 * 512], g_wf2l [128 * 512];

__device__ __forceinline__ void bsplit(float v, __nv_bfloat16& h, __nv_bfloat16& l) {
    h = __float2bfloat16(v);
    l = __float2bfloat16(v - __bfloat162float(h));
}

#define MMA_BF16(c, a, b) \
    asm volatile("mma.sync.aligned.m16n8k16.row.col.f32.bf16.bf16.f32 " \
        "{%0,%1,%2,%3}, {%4,%5,%6,%7}, {%8,%9}, {%0,%1,%2,%3};" \
        : "+f"((c)[0]), "+f"((c)[1]), "+f"((c)[2]), "+f"((c)[3]) \
        : "r"((a)[0]), "r"((a)[1]), "r"((a)[2]), "r"((a)[3]), \
          "r"((b)[0]), "r"((b)[1]))

// ---------------- K0: [B,C,HW] -> [B,HW,C] (+ bf16 hi/lo) ----------------
__global__ void k_transpose_in(const float* __restrict__ x) {
    __shared__ float tile[32][33];
    int b  = blockIdx.z;
    int p0 = blockIdx.x * 32;
    int c0 = blockIdx.y * 32;
    int tx = threadIdx.x, ty = threadIdx.y;
#pragma unroll
    for (int i = 0; i < 32; i += 8)
        tile[ty + i][tx] = x[(b * NC + c0 + ty + i) * NPIX + p0 + tx];
    __syncthreads();
#pragma unroll
    for (int i = 0; i < 32; i += 8) {
        float v = tile[tx][ty + i];
        size_t idx = (size_t)(b * NPIX + p0 + ty + i) * NC + c0 + tx;
        g_xt[idx] = v;
        __nv_bfloat16 h, l;
        bsplit(v, h, l);
        g_xth[idx] = h;
        g_xtl[idx] = l;
    }
}

// ---------------- K7: [B,HW,C] -> [B,C,HW] ----------------
__global__ void k_transpose_out(float* __restrict__ out) {
    __shared__ float tile[32][33];
    int b  = blockIdx.z;
    int p0 = blockIdx.x * 32;
    int c0 = blockIdx.y * 32;
    int tx = threadIdx.x, ty = threadIdx.y;
#pragma unroll
    for (int i = 0; i < 32; i += 8)
        tile[ty + i][tx] = g_y[(size_t)(b * NPIX + p0 + ty + i) * NC + c0 + tx];
    __syncthreads();
#pragma unroll
    for (int i = 0; i < 32; i += 8)
        out[(b * NC + c0 + ty + i) * NPIX + p0 + tx] = tile[tx][ty + i];
}

// ---------------- weight convert: W[K][N] fp32 -> Wt[N][K] bf16 hi/lo ----------------
// OP selects destination globals (no host symbol lookups needed).
template <int OP>
__global__ void k_wconv(const float* __restrict__ W) {
    constexpr int Kd = (OP == 3) ? 512 : 128;
    constexpr int Nd = (OP == 0) ? 384 : ((OP == 2) ? 512 : 128);
    __nv_bfloat16* Wh = (OP == 0) ? g_wqkvh : (OP == 1) ? g_wprjh : (OP == 2) ? g_wf1h : g_wf2h;
    __nv_bfloat16* Wl = (OP == 0) ? g_wqkvl : (OP == 1) ? g_wprjl : (OP == 2) ? g_wf1l : g_wf2l;
    int idx = blockIdx.x * 256 + threadIdx.x;
    if (idx >= Kd * Nd) return;
    int k = idx / Nd, n = idx % Nd;
    float v = W[idx];
    __nv_bfloat16 h, l;
    bsplit(v, h, l);
    Wh[n * Kd + k] = h;
    Wl[n * Kd + k] = l;
}

// ---------------- K1: meta-network relative-position bias ----------------
__global__ void k_meta_bias(const float* __restrict__ w1, const float* __restrict__ b1,
                            const float* __restrict__ w2, const float* __restrict__ b2) {
    int p = blockIdx.x * 256 + threadIdx.x;
    if (p >= TOK * TOK) return;
    int qi = p >> 6, kj = p & 63;
    float d0 = (float)((qi >> 3) - (kj >> 3));
    float d1 = (float)((qi & 7) - (kj & 7));
    float r0 = (d0 > 0.f) ? log1pf(d0) : (d0 < 0.f ? -log1pf(-d0) : 0.f);
    float r1 = (d1 > 0.f) ? log1pf(d1) : (d1 < 0.f ? -log1pf(-d1) : 0.f);
    float acc0 = 0.f, acc1 = 0.f, acc2 = 0.f, acc3 = 0.f;
    for (int j = 0; j < MH; j++) {
        float h = fmaf(r0, w1[j], fmaf(r1, w1[MH + j], b1[j]));
        h = fmaxf(h, 0.f);
        acc0 = fmaf(h, w2[j * 4 + 0], acc0);
        acc1 = fmaf(h, w2[j * 4 + 1], acc1);
        acc2 = fmaf(h, w2[j * 4 + 2], acc2);
        acc3 = fmaf(h, w2[j * 4 + 3], acc3);
    }
    g_bias[0 * 4096 + p] = acc0 + b2[0];
    g_bias[1 * 4096 + p] = acc1 + b2[1];
    g_bias[2 * 4096 + p] = acc2 + b2[2];
    g_bias[3 * 4096 + p] = acc3 + b2[3];
}

// ---------------- K3: windowed cosine attention (register-tiled) ----------------
__global__ void __launch_bounds__(256) k_attn(const float* __restrict__ tau) {
    __shared__ float sq[TOK][33];
    __shared__ float sk[TOK][33];
    __shared__ float sv[TOK][34];
    __shared__ float ss[TOK][65];
    __shared__ float sqn[TOK], skn[TOK];
    __shared__ int   sreg[TOK];

    int gw   = blockIdx.x;
    int head = blockIdx.y;
    int tid  = threadIdx.x;
    int win  = gw & 63;
    int wh   = win >> 3, ww = win & 7;
    int rowbase = gw * TOK;
    int qoff = head * DH;

    for (int idx = tid; idx < TOK * (DH / 4); idx += 256) {
        int t  = idx >> 3;
        int d4 = (idx & 7) * 4;
        const float* rp = g_qkv + (size_t)(rowbase + t) * (3 * NC);
        float4 q4 = *(const float4*)(rp + qoff + d4);
        float4 k4 = *(const float4*)(rp + NC + qoff + d4);
        float4 v4 = *(const float4*)(rp + 2 * NC + qoff + d4);
        sq[t][d4 + 0] = q4.x; sq[t][d4 + 1] = q4.y; sq[t][d4 + 2] = q4.z; sq[t][d4 + 3] = q4.w;
        sk[t][d4 + 0] = k4.x; sk[t][d4 + 1] = k4.y; sk[t][d4 + 2] = k4.z; sk[t][d4 + 3] = k4.w;
        sv[t][d4 + 0] = v4.x; sv[t][d4 + 1] = v4.y; sv[t][d4 + 2] = v4.z; sv[t][d4 + 3] = v4.w;
    }
    if (tid < TOK) {
        int th = tid >> 3, tw = tid & 7;
        int hs = wh * WSZ + th, wsc = ww * WSZ + tw;
        int rh = (hs  >= NH  - SHIFT) ? 2 : ((hs  >= NH  - WSZ) ? 1 : 0);
        int rw = (wsc >= NWp - SHIFT) ? 2 : ((wsc >= NWp - WSZ) ? 1 : 0);
        sreg[tid] = rh * 3 + rw;
    }
    __syncthreads();

    if (tid < TOK) {
        float s = 0.f;
#pragma unroll
        for (int d = 0; d < DH; d++) s = fmaf(sq[tid][d], sq[tid][d], s);
        sqn[tid] = sqrtf(s);
    } else if (tid < 2 * TOK) {
        int t = tid - TOK;
        float s = 0.f;
#pragma unroll
        for (int d = 0; d < DH; d++) s = fmaf(sk[t][d], sk[t][d], s);
        skn[t] = sqrtf(s);
    }
    __syncthreads();

    // scores: each thread computes a 4x4 tile
    {
        int ti = tid >> 4, tj = tid & 15;
        float c[4][4];
#pragma unroll
        for (int i = 0; i < 4; i++)
#pragma unroll
            for (int j = 0; j < 4; j++) c[i][j] = 0.f;
#pragma unroll
        for (int k = 0; k < DH; k++) {
            float a[4], b[4];
#pragma unroll
            for (int ii = 0; ii < 4; ii++) a[ii] = sq[ti * 4 + ii][k];
#pragma unroll
            for (int jj = 0; jj < 4; jj++) b[jj] = sk[tj * 4 + jj][k];
#pragma unroll
            for (int ii = 0; ii < 4; ii++)
#pragma unroll
                for (int jj = 0; jj < 4; jj++) c[ii][jj] = fmaf(a[ii], b[jj], c[ii][jj]);
        }
        float tinv = 1.0f / fmaxf(tau[head], 0.01f);
        const float* bptr = g_bias + head * TOK * TOK;
#pragma unroll
        for (int ii = 0; ii < 4; ii++) {
            int i = ti * 4 + ii;
#pragma unroll
            for (int jj = 0; jj < 4; jj++) {
                int j = tj * 4 + jj;
                float s = c[ii][jj] / fmaxf(sqn[i] * skn[j], 1e-6f) * tinv + bptr[(i << 6) + j];
                if (sreg[i] != sreg[j]) s -= 100.0f;
                ss[i][j] = s;
            }
        }
    }
    __syncthreads();

    // softmax: 4 threads per row
    {
        int r = tid >> 2, sub = tid & 3;
        int c0 = sub * 16;
        float mx = -1e30f;
#pragma unroll
        for (int c = 0; c < 16; c++) mx = fmaxf(mx, ss[r][c0 + c]);
        mx = fmaxf(mx, __shfl_xor_sync(0xffffffffu, mx, 1));
        mx = fmaxf(mx, __shfl_xor_sync(0xffffffffu, mx, 2));
        float sum = 0.f;
#pragma unroll
        for (int c = 0; c < 16; c++) {
            float e = expf(ss[r][c0 + c] - mx);
            ss[r][c0 + c] = e;
            sum += e;
        }
        sum += __shfl_xor_sync(0xffffffffu, sum, 1);
        sum += __shfl_xor_sync(0xffffffffu, sum, 2);
        float inv = 1.0f / sum;
#pragma unroll
        for (int c = 0; c < 16; c++) ss[r][c0 + c] *= inv;
    }
    __syncthreads();

    // AV: each thread computes 4 rows x 2 cols
    {
        int grp = tid >> 4, tj = tid & 15;
        int i0 = grp * 4, d0 = tj * 2;
        float o0[4], o1[4];
#pragma unroll
        for (int ii = 0; ii < 4; ii++) { o0[ii] = 0.f; o1[ii] = 0.f; }
#pragma unroll 8
        for (int j = 0; j < TOK; j++) {
            float2 bb = *(const float2*)&sv[j][d0];
#pragma unroll
            for (int ii = 0; ii < 4; ii++) {
                float a = ss[i0 + ii][j];
                o0[ii] = fmaf(a, bb.x, o0[ii]);
                o1[ii] = fmaf(a, bb.y, o1[ii]);
            }
        }
#pragma unroll
        for (int ii = 0; ii < 4; ii++) {
            int i = i0 + ii;
            __nv_bfloat16 h0, l0, h1, l1;
            bsplit(o0[ii], h0, l0);
            bsplit(o1[ii], h1, l1);
            __nv_bfloat162 hp; hp.x = h0; hp.y = h1;
            __nv_bfloat162 lp; lp.x = l0; lp.y = l1;
            size_t idx = (size_t)(rowbase + i) * NC + qoff + d0;
            *(__nv_bfloat162*)(g_atth + idx) = hp;
            *(__nv_bfloat162*)(g_attl + idx) = lp;
        }
    }
}

// ---------------- tensor-core GEMM: 128x128 CTA tile, 512 thr, warp 32x32 ----------------
// OP 0: QKV  (A = xt gathered via roll+window, N=384, K=128, +bias -> g_qkv fp32)
// OP 1: PROJ (A = att gathered, N=128, K=128, +bias, LN1, +xt residual -> skip fp32 + h/l)
// OP 2: FFN1 (A = skip, N=512, K=128, +bias, GELU -> ffn1 h/l)
// OP 3: FFN2 (A = ffn1, N=128, K=512, +bias, LN2, +skip residual -> y fp32)
template <int OP>
__global__ void __launch_bounds__(512, 1) k_gemm(const float* __restrict__ bias,
                                                 const float* __restrict__ lng,
                                                 const float* __restrict__ lnb) {
    constexpr int K    = (OP == 3) ? 512 : 128;
    constexpr int N    = (OP == 0) ? 384 : ((OP == 2) ? 512 : 128);
    constexpr int NKCH = K / 16;

    __shared__ alignas(16) __nv_bfloat16 sA[2][2][128][16];
    __shared__ alignas(16) __nv_bfloat16 sB[2][2][128][16];
    __shared__ int   srow[128];
    __shared__ float redS[128][4];
    __shared__ float redQ[128][4];

    const __nv_bfloat16* Ah = (OP == 0) ? g_xth : (OP == 1) ? g_atth : (OP == 2) ? g_skph : g_f1h;
    const __nv_bfloat16* Al = (OP == 0) ? g_xtl : (OP == 1) ? g_attl : (OP == 2) ? g_skpl : g_f1l;
    const __nv_bfloat16* Wh = (OP == 0) ? g_wqkvh : (OP == 1) ? g_wprjh : (OP == 2) ? g_wf1h : g_wf2h;
    const __nv_bfloat16* Wl = (OP == 0) ? g_wqkvl : (OP == 1) ? g_wprjl : (OP == 2) ? g_wf1l : g_wf2l;

    int tid = threadIdx.x;
    int m0  = blockIdx.x * 128;
    int n0  = blockIdx.y * 128;

    if (tid < 128) {
        int r = m0 + tid;
        int s;
        if (OP == 0) {
            int b = r >> 12, win = (r >> 6) & 63, t = r & 63;
            int hs = ((win >> 3) << 3) + (t >> 3);
            int ws = ((win & 7) << 3) + (t & 7);
            int hsrc = (hs + SHIFT) & 63, wsrc = (ws + SHIFT) & 63;
            s = (b << 12) + (hsrc << 6) + wsrc;
        } else if (OP == 1) {
            int b = r >> 12, h = (r >> 6) & 63, w = r & 63;
            int hs = (h - SHIFT) & 63, ws = (w - SHIFT) & 63;
            int win = ((hs >> 3) << 3) + (ws >> 3);
            int t   = ((hs & 7) << 3) + (ws & 7);
            s = (b << 12) + (win << 6) + t;
        } else {
            s = r;
        }
        srow[tid] = s;
    }
    __syncthreads();

    // ---- loader setup: warps 0-7 load A (hi+lo), warps 8-15 load B ----
    bool isA = tid < 256;
    int  lid = isA ? tid : tid - 256;
    int  lrow = lid >> 1, lhalf = lid & 1;
    const __nv_bfloat16 *pH, *pL;
    if (isA) {
        size_t base = (size_t)srow[lrow] * K + lhalf * 8;
        pH = Ah + base;
        pL = Al + base;
    } else {
        size_t base = (size_t)(n0 + lrow) * K + lhalf * 8;
        pH = Wh + base;
        pL = Wl + base;
    }

    uint4 rh = *(const uint4*)pH;
    uint4 rl = *(const uint4*)pL;
    if (isA) {
        *(uint4*)&sA[0][0][lrow][lhalf * 8] = rh;
        *(uint4*)&sA[0][1][lrow][lhalf * 8] = rl;
    } else {
        *(uint4*)&sB[0][0][lrow][lhalf * 8] = rh;
        *(uint4*)&sB[0][1][lrow][lhalf * 8] = rl;
    }
    __syncthreads();

    int w = tid >> 5, lane = tid & 31;
    int wm = w & 3, wn = w >> 2;              // 4 warps along M, 4 along N
    int rbase = wm * 32, cbase = wn * 32;
    int g = lane >> 2, t = lane & 3;

    float acc[2][4][4];
#pragma unroll
    for (int mi = 0; mi < 2; mi++)
#pragma unroll
        for (int ni = 0; ni < 4; ni++)
#pragma unroll
            for (int e = 0; e < 4; e++) acc[mi][ni][e] = 0.f;

    int buf = 0;
    for (int ch = 0; ch < NKCH; ch++) {
        if (ch + 1 < NKCH) {
            rh = *(const uint4*)(pH + (ch + 1) * 16);
            rl = *(const uint4*)(pL + (ch + 1) * 16);
        }
        uint32_t af[2][2][4], bf[2][4][2];
#pragma unroll
        for (int term = 0; term < 2; term++)
#pragma unroll
            for (int mi = 0; mi < 2; mi++) {
                int row0 = rbase + mi * 16 + g;
                af[term][mi][0] = *(const uint32_t*)&sA[buf][term][row0][t * 2];
                af[term][mi][1] = *(const uint32_t*)&sA[buf][term][row0 + 8][t * 2];
                af[term][mi][2] = *(const uint32_t*)&sA[buf][term][row0][t * 2 + 8];
                af[term][mi][3] = *(const uint32_t*)&sA[buf][term][row0 + 8][t * 2 + 8];
            }
#pragma unroll
        for (int term = 0; term < 2; term++)
#pragma unroll
            for (int ni = 0; ni < 4; ni++) {
                int nr = cbase + ni * 8 + g;
                bf[term][ni][0] = *(const uint32_t*)&sB[buf][term][nr][t * 2];
                bf[term][ni][1] = *(const uint32_t*)&sB[buf][term][nr][t * 2 + 8];
            }
#pragma unroll
        for (int mi = 0; mi < 2; mi++)
#pragma unroll
            for (int ni = 0; ni < 4; ni++) {
                MMA_BF16(acc[mi][ni], af[0][mi], bf[0][ni]);  // hi*hi
                MMA_BF16(acc[mi][ni], af[0][mi], bf[1][ni]);  // hi*lo
                MMA_BF16(acc[mi][ni], af[1][mi], bf[0][ni]);  // lo*hi
            }
        if (ch + 1 < NKCH) {
            int nb = buf ^ 1;
            if (isA) {
                *(uint4*)&sA[nb][0][lrow][lhalf * 8] = rh;
                *(uint4*)&sA[nb][1][lrow][lhalf * 8] = rl;
            } else {
                *(uint4*)&sB[nb][0][lrow][lhalf * 8] = rh;
                *(uint4*)&sB[nb][1][lrow][lhalf * 8] = rl;
            }
        }
        __syncthreads();
        buf ^= 1;
    }

    // ---- epilogue ----
    float2 bv[4];
#pragma unroll
    for (int ni = 0; ni < 4; ni++)
        bv[ni] = *(const float2*)(bias + n0 + cbase + ni * 8 + t * 2);
#pragma unroll
    for (int mi = 0; mi < 2; mi++)
#pragma unroll
        for (int ni = 0; ni < 4; ni++) {
            acc[mi][ni][0] += bv[ni].x;
            acc[mi][ni][1] += bv[ni].y;
            acc[mi][ni][2] += bv[ni].x;
            acc[mi][ni][3] += bv[ni].y;
        }

    if constexpr (OP == 0 || OP == 2) {
#pragma unroll
        for (int mi = 0; mi < 2; mi++) {
            int r0 = m0 + rbase + mi * 16 + g;
#pragma unroll
            for (int ni = 0; ni < 4; ni++) {
                int c = n0 + cbase + ni * 8 + t * 2;
                float v0 = acc[mi][ni][0], v1 = acc[mi][ni][1];
                float v2 = acc[mi][ni][2], v3 = acc[mi][ni][3];
                if constexpr (OP == 0) {
                    *(float2*)(g_qkv + (size_t)r0 * 384 + c)       = make_float2(v0, v1);
                    *(float2*)(g_qkv + (size_t)(r0 + 8) * 384 + c) = make_float2(v2, v3);
                } else {
                    v0 = 0.5f * v0 * (1.0f + erff(v0 * 0.70710678118654752f));
                    v1 = 0.5f * v1 * (1.0f + erff(v1 * 0.70710678118654752f));
                    v2 = 0.5f * v2 * (1.0f + erff(v2 * 0.70710678118654752f));
                    v3 = 0.5f * v3 * (1.0f + erff(v3 * 0.70710678118654752f));
                    __nv_bfloat16 h0, l0, h1, l1;
                    bsplit(v0, h0, l0); bsplit(v1, h1, l1);
                    __nv_bfloat162 hp, lp;
                    hp.x = h0; hp.y = h1; lp.x = l0; lp.y = l1;
                    *(__nv_bfloat162*)(g_f1h + (size_t)r0 * HID + c) = hp;
                    *(__nv_bfloat162*)(g_f1l + (size_t)r0 * HID + c) = lp;
                    bsplit(v2, h0, l0); bsplit(v3, h1, l1);
                    hp.x = h0; hp.y = h1; lp.x = l0; lp.y = l1;
                    *(__nv_bfloat162*)(g_f1h + (size_t)(r0 + 8) * HID + c) = hp;
                    *(__nv_bfloat162*)(g_f1l + (size_t)(r0 + 8) * HID + c) = lp;
                }
            }
        }
    } else {
        // LN epilogue (N == 128, n0 == 0)
        float sums[2][2] = {{0.f, 0.f}, {0.f, 0.f}};
        float sqs [2][2] = {{0.f, 0.f}, {0.f, 0.f}};
#pragma unroll
        for (int mi = 0; mi < 2; mi++)
#pragma unroll
            for (int ni = 0; ni < 4; ni++) {
                sums[mi][0] += acc[mi][ni][0] + acc[mi][ni][1];
                sqs [mi][0] += acc[mi][ni][0] * acc[mi][ni][0] + acc[mi][ni][1] * acc[mi][ni][1];
                sums[mi][1] += acc[mi][ni][2] + acc[mi][ni][3];
                sqs [mi][1] += acc[mi][ni][2] * acc[mi][ni][2] + acc[mi][ni][3] * acc[mi][ni][3];
            }
#pragma unroll
        for (int mi = 0; mi < 2; mi++)
#pragma unroll
            for (int h = 0; h < 2; h++) {
                sums[mi][h] += __shfl_xor_sync(0xffffffffu, sums[mi][h], 1);
                sums[mi][h] += __shfl_xor_sync(0xffffffffu, sums[mi][h], 2);
                sqs [mi][h] += __shfl_xor_sync(0xffffffffu, sqs [mi][h], 1);
                sqs [mi][h] += __shfl_xor_sync(0xffffffffu, sqs [mi][h], 2);
            }
        if (t == 0) {
#pragma unroll
            for (int mi = 0; mi < 2; mi++)
#pragma unroll
                for (int h = 0; h < 2; h++) {
                    int r = rbase + mi * 16 + g + h * 8;
                    redS[r][wn] = sums[mi][h];
                    redQ[r][wn] = sqs[mi][h];
                }
        }
        __syncthreads();

        float2 gv[4], bv2[4];
#pragma unroll
        for (int ni = 0; ni < 4; ni++) {
            gv[ni]  = *(const float2*)(lng + cbase + ni * 8 + t * 2);
            bv2[ni] = *(const float2*)(lnb + cbase + ni * 8 + t * 2);
        }
        const float* Rp = (OP == 1) ? g_xt : g_skip;
#pragma unroll
        for (int mi = 0; mi < 2; mi++)
#pragma unroll
            for (int h = 0; h < 2; h++) {
                int rl_ = rbase + mi * 16 + g + h * 8;
                int r = m0 + rl_;
                float S = redS[rl_][0] + redS[rl_][1] + redS[rl_][2] + redS[rl_][3];
                float Q = redQ[rl_][0] + redQ[rl_][1] + redQ[rl_][2] + redQ[rl_][3];
                float mean = S * (1.0f / 128.0f);
                float var  = Q * (1.0f / 128.0f) - mean * mean;
                float rstd = rsqrtf(var + 1e-5f);
#pragma unroll
                for (int ni = 0; ni < 4; ni++) {
                    int c = cbase + ni * 8 + t * 2;
                    int ia = h * 2;
                    float v0 = acc[mi][ni][ia + 0];
                    float v1 = acc[mi][ni][ia + 1];
                    float2 res = *(const float2*)(Rp + (size_t)r * 128 + c);
                    float o0 = (v0 - mean) * rstd * gv[ni].x + bv2[ni].x + res.x;
                    float o1 = (v1 - mean) * rstd * gv[ni].y + bv2[ni].y + res.y;
                    if constexpr (OP == 1) {
                        *(float2*)(g_skip + (size_t)r * 128 + c) = make_float2(o0, o1);
                        __nv_bfloat16 h0, l0, h1, l1;
                        bsplit(o0, h0, l0); bsplit(o1, h1, l1);
                        __nv_bfloat162 hp, lp;
                        hp.x = h0; hp.y = h1; lp.x = l0; lp.y = l1;
                        *(__nv_bfloat162*)(g_skph + (size_t)r * 128 + c) = hp;
                        *(__nv_bfloat162*)(g_skpl + (size_t)r * 128 + c) = lp;
                    } else {
                        *(float2*)(g_y + (size_t)r * 128 + c) = make_float2(o0, o1);
                    }
                }
            }
    }
}

// ---------------- launch ----------------
extern "C" void kernel_launch(void* const* d_in, const int* in_sizes, int n_in,
                              void* d_out, int out_size) {
    const float* x      = (const float*)d_in[0];
    const float* qkv_w  = (const float*)d_in[1];
    const float* qkv_b  = (const float*)d_in[2];
    const float* proj_w = (const float*)d_in[3];
    const float* proj_b = (const float*)d_in[4];
    const float* mw1    = (const float*)d_in[5];
    const float* mb1    = (const float*)d_in[6];
    const float* mw2    = (const float*)d_in[7];
    const float* mb2    = (const float*)d_in[8];
    const float* tau    = (const float*)d_in[9];
    const float* ln1g   = (const float*)d_in[10];
    const float* ln1b   = (const float*)d_in[11];
    const float* ln2g   = (const float*)d_in[12];
    const float* ln2b   = (const float*)d_in[13];
    const float* fw1    = (const float*)d_in[14];
    const float* fb1    = (const float*)d_in[15];
    const float* fw2    = (const float*)d_in[16];
    const float* fb2    = (const float*)d_in[17];
    float* out = (float*)d_out;

    dim3 tb(32, 8);
    k_transpose_in<<<dim3(NPIX / 32, NC / 32, NB), tb>>>(x);
    k_wconv<0><<<(128 * 384 + 255) / 256, 256>>>(qkv_w);
    k_wconv<1><<<(128 * 128 + 255) / 256, 256>>>(proj_w);
    k_wconv<2><<<(128 * 512 + 255) / 256, 256>>>(fw1);
    k_wconv<3><<<(512 * 128 + 255) / 256, 256>>>(fw2);
    k_meta_bias<<<16, 256>>>(mw1, mb1, mw2, mb2);
    k_gemm<0><<<dim3(NTOK / 128, 3), 512>>>(qkv_b, nullptr, nullptr);
    k_attn<<<dim3(NB * NWIN, NHEADS), 256>>>(tau);
    k_gemm<1><<<dim3(NTOK / 128, 1), 512>>>(proj_b, ln1g, ln1b);
    k_gemm<2><<<dim3(NTOK / 128, 4), 512>>>(fb1, nullptr, nullptr);
    k_gemm<3><<<dim3(NTOK / 128, 1), 512>>>(fb2, ln2g, ln2b);
    k_transpose_out<<<dim3(NPIX / 32, NC / 32, NB), tb>>>(out);
}

// round 6
// speedup vs baseline: 1.3382x; 1.1561x over previous
#include <cuda_runtime.h>
#include <cuda_bf16.h>
#include <math.h>
#include <stdint.h>

// ---------------- problem constants ----------------
constexpr int NB     = 32;
constexpr int NC     = 128;
constexpr int NH     = 64;
constexpr int NWp    = 64;
constexpr int WSZ    = 8;
constexpr int SHIFT  = 4;
constexpr int NHEADS = 4;
constexpr int DH     = 32;
constexpr int TOK    = 64;
constexpr int NWIN   = 64;
constexpr int NPIX   = NH * NWp;    // 4096
constexpr int NTOK   = NB * NPIX;   // 131072
constexpr int HID    = 512;
constexpr int MH     = 256;

// ---------------- device scratch ----------------
__device__ float g_xt  [NTOK * NC];
__device__ float g_qkv [NTOK * 3 * NC];
__device__ float g_skip[NTOK * NC];
__device__ float g_y   [NTOK * NC];
__device__ float g_bias[NHEADS * TOK * TOK];

__device__ __nv_bfloat16 g_xth [NTOK * NC];
__device__ __nv_bfloat16 g_xtl [NTOK * NC];
__device__ __nv_bfloat16 g_atth[NTOK * NC];
__device__ __nv_bfloat16 g_attl[NTOK * NC];
__device__ __nv_bfloat16 g_skph[NTOK * NC];
__device__ __nv_bfloat16 g_skpl[NTOK * NC];
__device__ __nv_bfloat16 g_f1h [NTOK * HID];
__device__ __nv_bfloat16 g_f1l [NTOK * HID];

__device__ __nv_bfloat16 g_wqkvh[384 * 128], g_wqkvl[384 * 128];
__device__ __nv_bfloat16 g_wprjh[128 * 128], g_wprjl[128 * 128];
__device__ __nv_bfloat16 g_wf1h [512 * 128], g_wf1l [512 * 128];
__device__ __nv_bfloat16 g_wf2h [128 * 512], g_wf2l [128 * 512];

__device__ __forceinline__ void bsplit(float v, __nv_bfloat16& h, __nv_bfloat16& l) {
    h = __float2bfloat16(v);
    l = __float2bfloat16(v - __bfloat162float(h));
}

__device__ __forceinline__ uint32_t smem_u32(const void* p) {
    uint32_t a;
    asm("{ .reg .u64 t; cvta.to.shared.u64 t, %1; cvt.u32.u64 %0, t; }" : "=r"(a) : "l"(p));
    return a;
}

#define MMA_BF16(c, a, b0v, b1v) \
    asm volatile("mma.sync.aligned.m16n8k16.row.col.f32.bf16.bf16.f32 " \
        "{%0,%1,%2,%3}, {%4,%5,%6,%7}, {%8,%9}, {%0,%1,%2,%3};" \
        : "+f"((c)[0]), "+f"((c)[1]), "+f"((c)[2]), "+f"((c)[3]) \
        : "r"((a)[0]), "r"((a)[1]), "r"((a)[2]), "r"((a)[3]), \
          "r"(b0v), "r"(b1v))

#define LDSM_X4(r, addr) \
    asm volatile("ldmatrix.sync.aligned.m8n8.x4.shared.b16 {%0,%1,%2,%3}, [%4];" \
        : "=r"((r)[0]), "=r"((r)[1]), "=r"((r)[2]), "=r"((r)[3]) : "r"(addr))

// ---------------- K0: [B,C,HW] -> [B,HW,C] (+ bf16 hi/lo) ----------------
__global__ void k_transpose_in(const float* __restrict__ x) {
    __shared__ float tile[32][33];
    int b  = blockIdx.z;
    int p0 = blockIdx.x * 32;
    int c0 = blockIdx.y * 32;
    int tx = threadIdx.x, ty = threadIdx.y;
#pragma unroll
    for (int i = 0; i < 32; i += 8)
        tile[ty + i][tx] = x[(b * NC + c0 + ty + i) * NPIX + p0 + tx];
    __syncthreads();
#pragma unroll
    for (int i = 0; i < 32; i += 8) {
        float v = tile[tx][ty + i];
        size_t idx = (size_t)(b * NPIX + p0 + ty + i) * NC + c0 + tx;
        g_xt[idx] = v;
        __nv_bfloat16 h, l;
        bsplit(v, h, l);
        g_xth[idx] = h;
        g_xtl[idx] = l;
    }
}

// ---------------- K7: [B,HW,C] -> [B,C,HW] ----------------
__global__ void k_transpose_out(float* __restrict__ out) {
    __shared__ float tile[32][33];
    int b  = blockIdx.z;
    int p0 = blockIdx.x * 32;
    int c0 = blockIdx.y * 32;
    int tx = threadIdx.x, ty = threadIdx.y;
#pragma unroll
    for (int i = 0; i < 32; i += 8)
        tile[ty + i][tx] = g_y[(size_t)(b * NPIX + p0 + ty + i) * NC + c0 + tx];
    __syncthreads();
#pragma unroll
    for (int i = 0; i < 32; i += 8)
        out[(b * NC + c0 + ty + i) * NPIX + p0 + tx] = tile[tx][ty + i];
}

// ---------------- weight convert: W[K][N] fp32 -> Wt[N][K] bf16 hi/lo ----------------
template <int OP>
__global__ void k_wconv(const float* __restrict__ W) {
    constexpr int Kd = (OP == 3) ? 512 : 128;
    constexpr int Nd = (OP == 0) ? 384 : ((OP == 2) ? 512 : 128);
    __nv_bfloat16* Wh = (OP == 0) ? g_wqkvh : (OP == 1) ? g_wprjh : (OP == 2) ? g_wf1h : g_wf2h;
    __nv_bfloat16* Wl = (OP == 0) ? g_wqkvl : (OP == 1) ? g_wprjl : (OP == 2) ? g_wf1l : g_wf2l;
    int idx = blockIdx.x * 256 + threadIdx.x;
    if (idx >= Kd * Nd) return;
    int k = idx / Nd, n = idx % Nd;
    float v = W[idx];
    __nv_bfloat16 h, l;
    bsplit(v, h, l);
    Wh[n * Kd + k] = h;
    Wl[n * Kd + k] = l;
}

// ---------------- K1: meta-network relative-position bias ----------------
__global__ void k_meta_bias(const float* __restrict__ w1, const float* __restrict__ b1,
                            const float* __restrict__ w2, const float* __restrict__ b2) {
    int p = blockIdx.x * 256 + threadIdx.x;
    if (p >= TOK * TOK) return;
    int qi = p >> 6, kj = p & 63;
    float d0 = (float)((qi >> 3) - (kj >> 3));
    float d1 = (float)((qi & 7) - (kj & 7));
    float r0 = (d0 > 0.f) ? log1pf(d0) : (d0 < 0.f ? -log1pf(-d0) : 0.f);
    float r1 = (d1 > 0.f) ? log1pf(d1) : (d1 < 0.f ? -log1pf(-d1) : 0.f);
    float acc0 = 0.f, acc1 = 0.f, acc2 = 0.f, acc3 = 0.f;
    for (int j = 0; j < MH; j++) {
        float h = fmaf(r0, w1[j], fmaf(r1, w1[MH + j], b1[j]));
        h = fmaxf(h, 0.f);
        acc0 = fmaf(h, w2[j * 4 + 0], acc0);
        acc1 = fmaf(h, w2[j * 4 + 1], acc1);
        acc2 = fmaf(h, w2[j * 4 + 2], acc2);
        acc3 = fmaf(h, w2[j * 4 + 3], acc3);
    }
    g_bias[0 * 4096 + p] = acc0 + b2[0];
    g_bias[1 * 4096 + p] = acc1 + b2[1];
    g_bias[2 * 4096 + p] = acc2 + b2[2];
    g_bias[3 * 4096 + p] = acc3 + b2[3];
}

// ---------------- K3: windowed cosine attention (register-tiled) ----------------
__global__ void __launch_bounds__(256) k_attn(const float* __restrict__ tau) {
    __shared__ float sq[TOK][33];
    __shared__ float sk[TOK][33];
    __shared__ float sv[TOK][34];
    __shared__ float ss[TOK][65];
    __shared__ float sqn[TOK], skn[TOK];
    __shared__ int   sreg[TOK];

    int gw   = blockIdx.x;
    int head = blockIdx.y;
    int tid  = threadIdx.x;
    int win  = gw & 63;
    int wh   = win >> 3, ww = win & 7;
    int rowbase = gw * TOK;
    int qoff = head * DH;

    for (int idx = tid; idx < TOK * (DH / 4); idx += 256) {
        int t  = idx >> 3;
        int d4 = (idx & 7) * 4;
        const float* rp = g_qkv + (size_t)(rowbase + t) * (3 * NC);
        float4 q4 = *(const float4*)(rp + qoff + d4);
        float4 k4 = *(const float4*)(rp + NC + qoff + d4);
        float4 v4 = *(const float4*)(rp + 2 * NC + qoff + d4);
        sq[t][d4 + 0] = q4.x; sq[t][d4 + 1] = q4.y; sq[t][d4 + 2] = q4.z; sq[t][d4 + 3] = q4.w;
        sk[t][d4 + 0] = k4.x; sk[t][d4 + 1] = k4.y; sk[t][d4 + 2] = k4.z; sk[t][d4 + 3] = k4.w;
        sv[t][d4 + 0] = v4.x; sv[t][d4 + 1] = v4.y; sv[t][d4 + 2] = v4.z; sv[t][d4 + 3] = v4.w;
    }
    if (tid < TOK) {
        int th = tid >> 3, tw = tid & 7;
        int hs = wh * WSZ + th, wsc = ww * WSZ + tw;
        int rh = (hs  >= NH  - SHIFT) ? 2 : ((hs  >= NH  - WSZ) ? 1 : 0);
        int rw = (wsc >= NWp - SHIFT) ? 2 : ((wsc >= NWp - WSZ) ? 1 : 0);
        sreg[tid] = rh * 3 + rw;
    }
    __syncthreads();

    if (tid < TOK) {
        float s = 0.f;
#pragma unroll
        for (int d = 0; d < DH; d++) s = fmaf(sq[tid][d], sq[tid][d], s);
        sqn[tid] = sqrtf(s);
    } else if (tid < 2 * TOK) {
        int t = tid - TOK;
        float s = 0.f;
#pragma unroll
        for (int d = 0; d < DH; d++) s = fmaf(sk[t][d], sk[t][d], s);
        skn[t] = sqrtf(s);
    }
    __syncthreads();

    {
        int ti = tid >> 4, tj = tid & 15;
        float c[4][4];
#pragma unroll
        for (int i = 0; i < 4; i++)
#pragma unroll
            for (int j = 0; j < 4; j++) c[i][j] = 0.f;
#pragma unroll
        for (int k = 0; k < DH; k++) {
            float a[4], b[4];
#pragma unroll
            for (int ii = 0; ii < 4; ii++) a[ii] = sq[ti * 4 + ii][k];
#pragma unroll
            for (int jj = 0; jj < 4; jj++) b[jj] = sk[tj * 4 + jj][k];
#pragma unroll
            for (int ii = 0; ii < 4; ii++)
#pragma unroll
                for (int jj = 0; jj < 4; jj++) c[ii][jj] = fmaf(a[ii], b[jj], c[ii][jj]);
        }
        float tinv = 1.0f / fmaxf(tau[head], 0.01f);
        const float* bptr = g_bias + head * TOK * TOK;
#pragma unroll
        for (int ii = 0; ii < 4; ii++) {
            int i = ti * 4 + ii;
#pragma unroll
            for (int jj = 0; jj < 4; jj++) {
                int j = tj * 4 + jj;
                float s = c[ii][jj] / fmaxf(sqn[i] * skn[j], 1e-6f) * tinv + bptr[(i << 6) + j];
                if (sreg[i] != sreg[j]) s -= 100.0f;
                ss[i][j] = s;
            }
        }
    }
    __syncthreads();

    {
        int r = tid >> 2, sub = tid & 3;
        int c0 = sub * 16;
        float mx = -1e30f;
#pragma unroll
        for (int c = 0; c < 16; c++) mx = fmaxf(mx, ss[r][c0 + c]);
        mx = fmaxf(mx, __shfl_xor_sync(0xffffffffu, mx, 1));
        mx = fmaxf(mx, __shfl_xor_sync(0xffffffffu, mx, 2));
        float sum = 0.f;
#pragma unroll
        for (int c = 0; c < 16; c++) {
            float e = expf(ss[r][c0 + c] - mx);
            ss[r][c0 + c] = e;
            sum += e;
        }
        sum += __shfl_xor_sync(0xffffffffu, sum, 1);
        sum += __shfl_xor_sync(0xffffffffu, sum, 2);
        float inv = 1.0f / sum;
#pragma unroll
        for (int c = 0; c < 16; c++) ss[r][c0 + c] *= inv;
    }
    __syncthreads();

    {
        int grp = tid >> 4, tj = tid & 15;
        int i0 = grp * 4, d0 = tj * 2;
        float o0[4], o1[4];
#pragma unroll
        for (int ii = 0; ii < 4; ii++) { o0[ii] = 0.f; o1[ii] = 0.f; }
#pragma unroll 8
        for (int j = 0; j < TOK; j++) {
            float2 bb = *(const float2*)&sv[j][d0];
#pragma unroll
            for (int ii = 0; ii < 4; ii++) {
                float a = ss[i0 + ii][j];
                o0[ii] = fmaf(a, bb.x, o0[ii]);
                o1[ii] = fmaf(a, bb.y, o1[ii]);
            }
        }
#pragma unroll
        for (int ii = 0; ii < 4; ii++) {
            int i = i0 + ii;
            __nv_bfloat16 h0, l0, h1, l1;
            bsplit(o0[ii], h0, l0);
            bsplit(o1[ii], h1, l1);
            __nv_bfloat162 hp; hp.x = h0; hp.y = h1;
            __nv_bfloat162 lp; lp.x = l0; lp.y = l1;
            size_t idx = (size_t)(rowbase + i) * NC + qoff + d0;
            *(__nv_bfloat162*)(g_atth + idx) = hp;
            *(__nv_bfloat162*)(g_attl + idx) = lp;
        }
    }
}

// ---------------- tensor-core GEMM (mma.sync + ldmatrix), 128x128 tile, 512 thr ----
// smem rows padded to 24 bf16 (48 B): bank step 12 -> conflict-free ldmatrix.
// Layout (dynamic smem): A tiles then B tiles, each [2 buf][2 term][128 rows][24 elems].
constexpr int G_ROWB   = 48;                         // bytes per padded row
constexpr int G_TERMB  = 128 * G_ROWB;               // 6144
constexpr int G_BUFB   = 2 * G_TERMB;                // 12288
constexpr int G_AB     = 2 * G_BUFB;                 // 24576 per operand
constexpr int GSMEM_DYN = 2 * G_AB;                  // 49152 (= 48KB)

template <int OP>
__global__ void __launch_bounds__(512, 1) k_gemm(const float* __restrict__ bias,
                                                 const float* __restrict__ lng,
                                                 const float* __restrict__ lnb) {
    constexpr int K    = (OP == 3) ? 512 : 128;
    constexpr int N    = (OP == 0) ? 384 : ((OP == 2) ? 512 : 128);
    constexpr int NKCH = K / 16;

    extern __shared__ __align__(16) char dyn[];
    __shared__ int   srow[128];
    __shared__ float redS[128][4];
    __shared__ float redQ[128][4];

    const __nv_bfloat16* Ah = (OP == 0) ? g_xth : (OP == 1) ? g_atth : (OP == 2) ? g_skph : g_f1h;
    const __nv_bfloat16* Al = (OP == 0) ? g_xtl : (OP == 1) ? g_attl : (OP == 2) ? g_skpl : g_f1l;
    const __nv_bfloat16* Wh = (OP == 0) ? g_wqkvh : (OP == 1) ? g_wprjh : (OP == 2) ? g_wf1h : g_wf2h;
    const __nv_bfloat16* Wl = (OP == 0) ? g_wqkvl : (OP == 1) ? g_wprjl : (OP == 2) ? g_wf1l : g_wf2l;

    int tid = threadIdx.x;
    int m0  = blockIdx.x * 128;
    int n0  = blockIdx.y * 128;

    if (tid < 128) {
        int r = m0 + tid;
        int s;
        if (OP == 0) {
            int b = r >> 12, win = (r >> 6) & 63, t = r & 63;
            int hs = ((win >> 3) << 3) + (t >> 3);
            int ws = ((win & 7) << 3) + (t & 7);
            s = (b << 12) + (((hs + SHIFT) & 63) << 6) + ((ws + SHIFT) & 63);
        } else if (OP == 1) {
            int b = r >> 12, h = (r >> 6) & 63, w = r & 63;
            int hs = (h - SHIFT) & 63, ws = (w - SHIFT) & 63;
            s = (b << 12) + ((((hs >> 3) << 3) + (ws >> 3)) << 6) + (((hs & 7) << 3) + (ws & 7));
        } else {
            s = r;
        }
        srow[tid] = s;
    }
    __syncthreads();

    // ---- loaders: threads 0-255 -> A (hi+lo), 256-511 -> B ----
    bool isA  = tid < 256;
    int  lid  = isA ? tid : tid - 256;
    int  lrow = lid >> 1, lhalf = lid & 1;
    const __nv_bfloat16 *pH, *pL;
    if (isA) {
        size_t base = (size_t)srow[lrow] * K + lhalf * 8;
        pH = Ah + base;
        pL = Al + base;
    } else {
        size_t base = (size_t)(n0 + lrow) * K + lhalf * 8;
        pH = Wh + base;
        pL = Wl + base;
    }
    char* sput = dyn + (isA ? 0 : G_AB) + lrow * G_ROWB + lhalf * 16;

    uint4 rh = *(const uint4*)pH;
    uint4 rl = *(const uint4*)pL;
    *(uint4*)(sput + 0 * G_TERMB) = rh;       // buf0 term0 (hi)
    *(uint4*)(sput + 1 * G_TERMB) = rl;       // buf0 term1 (lo)
    __syncthreads();

    // ---- compute setup: 16 warps, 4x4 grid, warp tile 32x32 ----
    int w = tid >> 5, lane = tid & 31;
    int wm = w & 3, wn = w >> 2;
    int rbase = wm * 32, cbase = wn * 32;
    int g = lane >> 2, t = lane & 3;

    uint32_t dynu = smem_u32(dyn);
    uint32_t lr   = lane & 15;
    uint32_t lcol = (lane >> 4) * 16;
    uint32_t aBase = dynu + (rbase + lr) * G_ROWB + lcol;
    uint32_t bBase = dynu + G_AB + (cbase + lr) * G_ROWB + lcol;
    constexpr uint32_t MI_STRIDE = 16 * G_ROWB;   // 768

    float acc[2][4][4];
#pragma unroll
    for (int mi = 0; mi < 2; mi++)
#pragma unroll
        for (int ni = 0; ni < 4; ni++)
#pragma unroll
            for (int e = 0; e < 4; e++) acc[mi][ni][e] = 0.f;

    int buf = 0;
    for (int ch = 0; ch < NKCH; ch++) {
        if (ch + 1 < NKCH) {
            rh = *(const uint4*)(pH + (ch + 1) * 16);
            rl = *(const uint4*)(pL + (ch + 1) * 16);
        }
        // fragments via ldmatrix
        uint32_t af[2][2][4], bq[2][2][4];
        uint32_t bufOff = (uint32_t)buf * G_BUFB;
#pragma unroll
        for (int term = 0; term < 2; term++) {
            uint32_t to = bufOff + (uint32_t)term * G_TERMB;
#pragma unroll
            for (int mi = 0; mi < 2; mi++)
                LDSM_X4(af[term][mi], aBase + to + mi * MI_STRIDE);
#pragma unroll
            for (int bh = 0; bh < 2; bh++)
                LDSM_X4(bq[term][bh], bBase + to + bh * MI_STRIDE);
        }
        // write next buffer while MMAs run
        if (ch + 1 < NKCH) {
            char* p = sput + (buf ^ 1) * G_BUFB;
            *(uint4*)(p + 0 * G_TERMB) = rh;
            *(uint4*)(p + 1 * G_TERMB) = rl;
        }
#pragma unroll
        for (int mi = 0; mi < 2; mi++)
#pragma unroll
            for (int ni = 0; ni < 4; ni++) {
                int bh = ni >> 1, bi = ni & 1;
                MMA_BF16(acc[mi][ni], af[0][mi], bq[0][bh][bi], bq[0][bh][bi + 2]); // hi*hi
                MMA_BF16(acc[mi][ni], af[0][mi], bq[1][bh][bi], bq[1][bh][bi + 2]); // hi*lo
                MMA_BF16(acc[mi][ni], af[1][mi], bq[0][bh][bi], bq[0][bh][bi + 2]); // lo*hi
            }
        __syncthreads();
        buf ^= 1;
    }

    // ---- epilogue (same mapping as R4, validated) ----
    float2 bv[4];
#pragma unroll
    for (int ni = 0; ni < 4; ni++)
        bv[ni] = *(const float2*)(bias + n0 + cbase + ni * 8 + t * 2);
#pragma unroll
    for (int mi = 0; mi < 2; mi++)
#pragma unroll
        for (int ni = 0; ni < 4; ni++) {
            acc[mi][ni][0] += bv[ni].x;
            acc[mi][ni][1] += bv[ni].y;
            acc[mi][ni][2] += bv[ni].x;
            acc[mi][ni][3] += bv[ni].y;
        }

    if constexpr (OP == 0 || OP == 2) {
#pragma unroll
        for (int mi = 0; mi < 2; mi++) {
            int r0 = m0 + rbase + mi * 16 + g;
#pragma unroll
            for (int ni = 0; ni < 4; ni++) {
                int c = n0 + cbase + ni * 8 + t * 2;
                float v0 = acc[mi][ni][0], v1 = acc[mi][ni][1];
                float v2 = acc[mi][ni][2], v3 = acc[mi][ni][3];
                if constexpr (OP == 0) {
                    *(float2*)(g_qkv + (size_t)r0 * 384 + c)       = make_float2(v0, v1);
                    *(float2*)(g_qkv + (size_t)(r0 + 8) * 384 + c) = make_float2(v2, v3);
                } else {
                    v0 = 0.5f * v0 * (1.0f + erff(v0 * 0.70710678118654752f));
                    v1 = 0.5f * v1 * (1.0f + erff(v1 * 0.70710678118654752f));
                    v2 = 0.5f * v2 * (1.0f + erff(v2 * 0.70710678118654752f));
                    v3 = 0.5f * v3 * (1.0f + erff(v3 * 0.70710678118654752f));
                    __nv_bfloat16 h0, l0, h1, l1;
                    bsplit(v0, h0, l0); bsplit(v1, h1, l1);
                    __nv_bfloat162 hp, lp;
                    hp.x = h0; hp.y = h1; lp.x = l0; lp.y = l1;
                    *(__nv_bfloat162*)(g_f1h + (size_t)r0 * HID + c) = hp;
                    *(__nv_bfloat162*)(g_f1l + (size_t)r0 * HID + c) = lp;
                    bsplit(v2, h0, l0); bsplit(v3, h1, l1);
                    hp.x = h0; hp.y = h1; lp.x = l0; lp.y = l1;
                    *(__nv_bfloat162*)(g_f1h + (size_t)(r0 + 8) * HID + c) = hp;
                    *(__nv_bfloat162*)(g_f1l + (size_t)(r0 + 8) * HID + c) = lp;
                }
            }
        }
    } else {
        // LN epilogue (N == 128, n0 == 0)
        float sums[2][2] = {{0.f, 0.f}, {0.f, 0.f}};
        float sqs [2][2] = {{0.f, 0.f}, {0.f, 0.f}};
#pragma unroll
        for (int mi = 0; mi < 2; mi++)
#pragma unroll
            for (int ni = 0; ni < 4; ni++) {
                sums[mi][0] += acc[mi][ni][0] + acc[mi][ni][1];
                sqs [mi][0] += acc[mi][ni][0] * acc[mi][ni][0] + acc[mi][ni][1] * acc[mi][ni][1];
                sums[mi][1] += acc[mi][ni][2] + acc[mi][ni][3];
                sqs [mi][1] += acc[mi][ni][2] * acc[mi][ni][2] + acc[mi][ni][3] * acc[mi][ni][3];
            }
#pragma unroll
        for (int mi = 0; mi < 2; mi++)
#pragma unroll
            for (int h = 0; h < 2; h++) {
                sums[mi][h] += __shfl_xor_sync(0xffffffffu, sums[mi][h], 1);
                sums[mi][h] += __shfl_xor_sync(0xffffffffu, sums[mi][h], 2);
                sqs [mi][h] += __shfl_xor_sync(0xffffffffu, sqs [mi][h], 1);
                sqs [mi][h] += __shfl_xor_sync(0xffffffffu, sqs [mi][h], 2);
            }
        if (t == 0) {
#pragma unroll
            for (int mi = 0; mi < 2; mi++)
#pragma unroll
                for (int h = 0; h < 2; h++) {
                    int r = rbase + mi * 16 + g + h * 8;
                    redS[r][wn] = sums[mi][h];
                    redQ[r][wn] = sqs[mi][h];
                }
        }
        __syncthreads();

        float2 gv[4], bv2[4];
#pragma unroll
        for (int ni = 0; ni < 4; ni++) {
            gv[ni]  = *(const float2*)(lng + cbase + ni * 8 + t * 2);
            bv2[ni] = *(const float2*)(lnb + cbase + ni * 8 + t * 2);
        }
        const float* Rp = (OP == 1) ? g_xt : g_skip;
#pragma unroll
        for (int mi = 0; mi < 2; mi++)
#pragma unroll
            for (int h = 0; h < 2; h++) {
                int rl_ = rbase + mi * 16 + g + h * 8;
                int r = m0 + rl_;
                float S = redS[rl_][0] + redS[rl_][1] + redS[rl_][2] + redS[rl_][3];
                float Q = redQ[rl_][0] + redQ[rl_][1] + redQ[rl_][2] + redQ[rl_][3];
                float mean = S * (1.0f / 128.0f);
                float var  = Q * (1.0f / 128.0f) - mean * mean;
                float rstd = rsqrtf(var + 1e-5f);
#pragma unroll
                for (int ni = 0; ni < 4; ni++) {
                    int c = cbase + ni * 8 + t * 2;
                    int ia = h * 2;
                    float v0 = acc[mi][ni][ia + 0];
                    float v1 = acc[mi][ni][ia + 1];
                    float2 res = *(const float2*)(Rp + (size_t)r * 128 + c);
                    float o0 = (v0 - mean) * rstd * gv[ni].x + bv2[ni].x + res.x;
                    float o1 = (v1 - mean) * rstd * gv[ni].y + bv2[ni].y + res.y;
                    if constexpr (OP == 1) {
                        *(float2*)(g_skip + (size_t)r * 128 + c) = make_float2(o0, o1);
                        __nv_bfloat16 h0, l0, h1, l1;
                        bsplit(o0, h0, l0); bsplit(o1, h1, l1);
                        __nv_bfloat162 hp, lp;
                        hp.x = h0; hp.y = h1; lp.x = l0; lp.y = l1;
                        *(__nv_bfloat162*)(g_skph + (size_t)r * 128 + c) = hp;
                        *(__nv_bfloat162*)(g_skpl + (size_t)r * 128 + c) = lp;
                    } else {
                        *(float2*)(g_y + (size_t)r * 128 + c) = make_float2(o0, o1);
                    }
                }
            }
    }
}

// ---------------- launch ----------------
extern "C" void kernel_launch(void* const* d_in, const int* in_sizes, int n_in,
                              void* d_out, int out_size) {
    const float* x      = (const float*)d_in[0];
    const float* qkv_w  = (const float*)d_in[1];
    const float* qkv_b  = (const float*)d_in[2];
    const float* proj_w = (const float*)d_in[3];
    const float* proj_b = (const float*)d_in[4];
    const float* mw1    = (const float*)d_in[5];
    const float* mb1    = (const float*)d_in[6];
    const float* mw2    = (const float*)d_in[7];
    const float* mb2    = (const float*)d_in[8];
    const float* tau    = (const float*)d_in[9];
    const float* ln1g   = (const float*)d_in[10];
    const float* ln1b   = (const float*)d_in[11];
    const float* ln2g   = (const float*)d_in[12];
    const float* ln2b   = (const float*)d_in[13];
    const float* fw1    = (const float*)d_in[14];
    const float* fb1    = (const float*)d_in[15];
    const float* fw2    = (const float*)d_in[16];
    const float* fb2    = (const float*)d_in[17];
    float* out = (float*)d_out;

    cudaFuncSetAttribute(k_gemm<0>, cudaFuncAttributeMaxDynamicSharedMemorySize, GSMEM_DYN);
    cudaFuncSetAttribute(k_gemm<1>, cudaFuncAttributeMaxDynamicSharedMemorySize, GSMEM_DYN);
    cudaFuncSetAttribute(k_gemm<2>, cudaFuncAttributeMaxDynamicSharedMemorySize, GSMEM_DYN);
    cudaFuncSetAttribute(k_gemm<3>, cudaFuncAttributeMaxDynamicSharedMemorySize, GSMEM_DYN);

    dim3 tb(32, 8);
    k_transpose_in<<<dim3(NPIX / 32, NC / 32, NB), tb>>>(x);                       // 0
    k_wconv<0><<<(128 * 384 + 255) / 256, 256>>>(qkv_w);                           // 1
    k_wconv<1><<<(128 * 128 + 255) / 256, 256>>>(proj_w);                          // 2
    k_wconv<2><<<(128 * 512 + 255) / 256, 256>>>(fw1);                             // 3
    k_wconv<3><<<(512 * 128 + 255) / 256, 256>>>(fw2);                             // 4
    k_gemm<0><<<dim3(NTOK / 128, 3), 512, GSMEM_DYN>>>(qkv_b, nullptr, nullptr);   // 5 (ncu)
    k_meta_bias<<<16, 256>>>(mw1, mb1, mw2, mb2);                                  // 6
    k_attn<<<dim3(NB * NWIN, NHEADS), 256>>>(tau);                                 // 7
    k_gemm<1><<<dim3(NTOK / 128, 1), 512, GSMEM_DYN>>>(proj_b, ln1g, ln1b);        // 8
    k_gemm<2><<<dim3(NTOK / 128, 4), 512, GSMEM_DYN>>>(fb1, nullptr, nullptr);     // 9
    k_gemm<3><<<dim3(NTOK / 128, 1), 512, GSMEM_DYN>>>(fb2, ln2g, ln2b);           // 10
    k_transpose_out<<<dim3(NPIX / 32, NC / 32, NB), tb>>>(out);                    // 11
}